// round 1
// baseline (speedup 1.0000x reference)
#include <cuda_runtime.h>

// Correlation cost volume: B=8, C=128, H=W=128, max_disp=4 -> 81 displacements.
// out[b, dy*9+dx, y, x] = (1/C) sum_c in1[b,c,y,x] * in2[b,c,y+dy-4,x+dx-4] (zero pad)
//
// Design:
//  - Block = (b, 2 output rows). 9 warps: warp w handles displacement row dy=w.
//  - Thread: 8 consecutive x pixels (lane&15 -> x block, lane>>4 -> row), 9 dx
//    accumulators per pixel => 72 fp32 accumulators in registers.
//  - Channels processed in chunks of 16 through shared memory.
//  - Shared tiles stored block-transposed [k in 0..7][xblock] with lane-stride-1
//    words and +16-word row padding -> all compute LDS.32 are conflict-free.
//  - in1 pre-scaled by 1/128 on load (folds the mean).
//  - Output staged through shared memory for fully coalesced global stores.

#define BB 8
#define CC 128
#define HH 128
#define WW 128
#define MD 4
#define ND 9            // 2*MD+1
#define NDD 81
#define TY 2            // output rows per block
#define CH 16           // channels per shared chunk
#define NCHUNK (CC / CH)
#define THREADS 288     // 9 warps (one per dy)

#define S2_RI (TY + 2 * MD)     // 10 input rows per tile
#define S2_STRIDE 144           // 8*17 = 136, padded to 144 (stride % 32 == 16)
#define S1_STRIDE 144           // 8*16 = 128, padded to 144 (stride % 32 == 16)

#define S1_WORDS (CH * TY * S1_STRIDE)        // 4608
#define S2_WORDS (CH * S2_RI * S2_STRIDE)     // 23040
#define STAGE_WORDS (NDD * TY * WW)           // 20736 (fits in tile area)
#define SMEM_WORDS (S1_WORDS + S2_WORDS)      // 27648
#define SMEM_BYTES (SMEM_WORDS * 4)           // 110592

__global__ __launch_bounds__(THREADS, 1)
void corr_kernel(const float* __restrict__ in1,
                 const float* __restrict__ in2,
                 float* __restrict__ out)
{
    extern __shared__ float sm[];
    float* s1t = sm;              // [CH][TY][k=8][16 xblocks] padded rows
    float* s2t = sm + S1_WORDS;   // [CH][10 ri][k=8][17 xblocks] padded rows

    const int ytile = blockIdx.x;           // 0..63
    const int b     = blockIdx.y;           // 0..7
    const int y0    = ytile * TY;

    const int tid  = threadIdx.x;
    const int w    = tid >> 5;              // warp id == dy index (0..8)
    const int lane = tid & 31;
    const int tr   = lane >> 4;             // row within tile (0..1)
    const int lb   = lane & 15;             // x block: pixels x = 8*lb + j

    float acc[ND][8];
#pragma unroll
    for (int dx = 0; dx < ND; ++dx)
#pragma unroll
        for (int j = 0; j < 8; ++j) acc[dx][j] = 0.0f;

    for (int cc = 0; cc < NCHUNK; ++cc) {
        __syncthreads();   // previous chunk's readers done before overwrite

        // ---- load in1 tile (scaled by 1/C), block-transposed ----
        {
            const float* g1 = in1 + (((size_t)b * CC + cc * CH) * HH + y0) * WW;
            for (int i = tid; i < CH * TY * WW; i += THREADS) {
                int c   = i >> 8;          // / (TY*WW)
                int rem = i & 255;
                int row = rem >> 7;
                int x   = rem & 127;
                float v = g1[((size_t)c * HH + row) * WW + x] * (1.0f / 128.0f);
                s1t[(c * TY + row) * S1_STRIDE + (x & 7) * 16 + (x >> 3)] = v;
            }
        }

        // ---- load in2 tile (10 rows, x padded to 136 with zeros) ----
        {
            const float* g2 = in2 + ((size_t)b * CC + cc * CH) * HH * WW;
            for (int i = tid; i < CH * S2_RI * 136; i += THREADS) {
                int c   = i / (S2_RI * 136);
                int rem = i - c * (S2_RI * 136);
                int ri  = rem / 136;
                int p   = rem - ri * 136;
                int gy  = y0 - MD + ri;
                int gx  = p - MD;
                float v = 0.0f;
                if ((unsigned)gy < HH && (unsigned)gx < WW)
                    v = g2[((size_t)c * HH + gy) * WW + gx];
                s2t[(c * S2_RI + ri) * S2_STRIDE + (p & 7) * 17 + (p >> 3)] = v;
            }
        }

        __syncthreads();

        // ---- compute: this warp's dy row, 8 pixels, 9 dx ----
        const int ri = tr + w;   // 0..9
#pragma unroll 2
        for (int c = 0; c < CH; ++c) {
            const float* s1p = s1t + (c * TY + tr) * S1_STRIDE;
            const float* s2p = s2t + (c * S2_RI + ri) * S2_STRIDE;

            float a[8], f[16];
#pragma unroll
            for (int j = 0; j < 8; ++j)
                a[j] = s1p[j * 16 + lb];
#pragma unroll
            for (int m = 0; m < 16; ++m)
                f[m] = s2p[(m & 7) * 17 + lb + (m >> 3)];

#pragma unroll
            for (int dx = 0; dx < ND; ++dx)
#pragma unroll
                for (int j = 0; j < 8; ++j)
                    acc[dx][j] = fmaf(a[j], f[j + dx], acc[dx][j]);
        }
    }

    // ---- stage results in shared, then coalesced global stores ----
    __syncthreads();
    {
        float* so = sm;  // [81][TY][WW]
#pragma unroll
        for (int dx = 0; dx < ND; ++dx) {
            int d = w * ND + dx;
#pragma unroll
            for (int j = 0; j < 8; ++j)
                so[(d * TY + tr) * WW + lb * 8 + j] = acc[dx][j];
        }
    }
    __syncthreads();
    {
        const float* so = sm;
        float* op = out + ((size_t)b * NDD * HH + y0) * WW;
        for (int i = tid; i < STAGE_WORDS; i += THREADS) {
            int d   = i >> 8;          // / (TY*WW)
            int rem = i & 255;
            int row = rem >> 7;
            int x   = rem & 127;
            op[((size_t)d * HH + row) * WW + x] = so[i];
        }
    }
}

extern "C" void kernel_launch(void* const* d_in, const int* in_sizes, int n_in,
                              void* d_out, int out_size)
{
    (void)in_sizes; (void)n_in; (void)out_size;
    cudaFuncSetAttribute(corr_kernel,
                         cudaFuncAttributeMaxDynamicSharedMemorySize, SMEM_BYTES);
    const float* in1 = (const float*)d_in[0];
    const float* in2 = (const float*)d_in[1];
    float* out = (float*)d_out;
    corr_kernel<<<dim3(HH / TY, BB), THREADS, SMEM_BYTES>>>(in1, in2, out);
}

// round 2
// speedup vs baseline: 2.2716x; 2.2716x over previous
#include <cuda_runtime.h>
#include <cstdint>

// Correlation cost volume: B=8, C=128, H=W=128, max_disp=4 -> 81 displacements.
// out[b, dy*9+dx, y, x] = (1/C) sum_c in1[b,c,y,x] * in2[b,c,y+dy-4,x+dx-4]  (zero pad)
//
// R2 design:
//  - Block = (b, 2 output rows). 9 warps: warp w = displacement row dy.
//  - Thread: 8 consecutive x pixels, 9 dx accumulators each (72 fp32 regs).
//  - cp.async 3-stage pipeline over channel chunks of 4 (32 chunks),
//    CUTLASS order: wait(1) -> sync -> issue cc+2 -> compute cc.
//  - Division-free loaders; block-transposed smem (conflict-free LDS.32).
//  - Direct coalesced float4 stores; mean (1/128) folded into epilogue.

#define BB 8
#define CC 128
#define HH 128
#define WW 128
#define MD 4
#define ND 9
#define NDD 81
#define TY 2
#define CH 4
#define NCHUNK (CC / CH)        // 32
#define THREADS 288             // 9 warps
#define STAGES 3

#define S2_RI (TY + 2 * MD)     // 10 in2 rows per tile
#define S1_STRIDE 144           // 8*16=128 padded (stride % 32 == 16)
#define S2_STRIDE 144           // 8*17=136 padded

#define S1_WORDS (CH * TY * S1_STRIDE)      // 1152
#define S2_WORDS (CH * S2_RI * S2_STRIDE)   // 5760
#define STAGE_WORDS (S1_WORDS + S2_WORDS)   // 6912
#define SMEM_BYTES (STAGES * STAGE_WORDS * 4)   // 82944

__device__ __forceinline__ void cp4(uint32_t dst, const float* src, int srcsz) {
    asm volatile("cp.async.ca.shared.global [%0], [%1], 4, %2;\n"
                 :: "r"(dst), "l"(src), "r"(srcsz));
}
__device__ __forceinline__ void cp_commit() {
    asm volatile("cp.async.commit_group;\n");
}
#define CP_WAIT(n) asm volatile("cp.async.wait_group %0;\n" :: "n"(n))

// Load channel-chunk cc into the stage at shared address sbase.
__device__ __forceinline__ void load_chunk(
    int cc, uint32_t sbase,
    const float* __restrict__ in1, const float* __restrict__ in2,
    int b, int y0, int tid, int w, int lane)
{
    // ---- in1 tile: CH*TY rows of 128 contiguous floats ----
    const float* g1 = in1 + (((size_t)b * CC + cc * CH) * HH + y0) * WW;
#pragma unroll
    for (int i = tid; i < CH * TY * WW; i += THREADS) {
        int c   = i >> 8;           // / (TY*WW)
        int row = (i >> 7) & 1;
        int x   = i & 127;
        uint32_t dst = sbase + 4u * ((c * TY + row) * S1_STRIDE + (x & 7) * 16 + (x >> 3));
        cp4(dst, g1 + ((size_t)c * HH + row) * WW + x, 4);
    }

    // ---- in2 tile: CH*10 rows of 136 (zero padded edges) ----
    uint32_t s2b = sbase + 4u * S1_WORDS;
    const float* g2 = in2 + ((size_t)b * CC + cc * CH) * HH * WW;
    int ri = w, c = 0;          // r = c*10 + ri, starting at r = w, step 9
    for (int r = w; r < CH * S2_RI; r += ND) {
        int gy = y0 - MD + ri;
        int yok = ((unsigned)gy < HH) ? 1 : 0;
        const float* grow = g2 + ((size_t)c * HH + gy) * WW;
        uint32_t drow = s2b + 4u * ((c * S2_RI + ri) * S2_STRIDE);
#pragma unroll
        for (int p = lane; p < 136; p += 32) {
            int gx = p - MD;
            int ok = (yok && (unsigned)gx < WW) ? 4 : 0;
            const float* src = ok ? (grow + gx) : g2;   // clamp addr when masked
            cp4(drow + 4u * ((p & 7) * 17 + (p >> 3)), src, ok);
        }
        ri += ND;
        if (ri >= S2_RI) { ri -= S2_RI; ++c; }
    }
}

__global__ __launch_bounds__(THREADS, 2)
void corr_kernel(const float* __restrict__ in1,
                 const float* __restrict__ in2,
                 float* __restrict__ out)
{
    extern __shared__ float sm[];
    const uint32_t smb = (uint32_t)__cvta_generic_to_shared(sm);

    const int ytile = blockIdx.x;
    const int b     = blockIdx.y;
    const int y0    = ytile * TY;

    const int tid  = threadIdx.x;
    const int w    = tid >> 5;              // dy index (0..8)
    const int lane = tid & 31;
    const int tr   = lane >> 4;             // row within tile (0..1)
    const int lb   = lane & 15;             // x block: pixels x = 8*lb + j
    const int ri   = tr + w;                // in2 row index inside tile

    float acc[ND][8];
#pragma unroll
    for (int dx = 0; dx < ND; ++dx)
#pragma unroll
        for (int j = 0; j < 8; ++j) acc[dx][j] = 0.0f;

    // prologue: stages 0 and 1
    load_chunk(0, smb, in1, in2, b, y0, tid, w, lane);
    cp_commit();
    load_chunk(1, smb + STAGE_WORDS * 4, in1, in2, b, y0, tid, w, lane);
    cp_commit();

    int s_cur = 0;   // stage holding chunk cc
    for (int cc = 0; cc < NCHUNK; ++cc) {
        CP_WAIT(1);          // chunk cc's group complete (this thread)
        __syncthreads();     // all threads' copies visible; prev compute done

        int nx = cc + 2;
        if (nx < NCHUNK) {
            int s_nx = s_cur + 2; if (s_nx >= STAGES) s_nx -= STAGES;
            load_chunk(nx, smb + s_nx * (STAGE_WORDS * 4), in1, in2, b, y0, tid, w, lane);
        }
        cp_commit();         // commit every iteration (possibly empty group)

        // ---- compute chunk cc ----
        const float* st = sm + s_cur * STAGE_WORDS;
        const float* s1 = st + tr * S1_STRIDE + lb;
        const float* s2 = st + S1_WORDS + ri * S2_STRIDE + lb;
#pragma unroll
        for (int c = 0; c < CH; ++c) {
            float a[8], f[16];
#pragma unroll
            for (int j = 0; j < 8; ++j)
                a[j] = s1[c * (TY * S1_STRIDE) + j * 16];
#pragma unroll
            for (int m = 0; m < 16; ++m)
                f[m] = s2[c * (S2_RI * S2_STRIDE) + (m & 7) * 17 + (m >> 3)];
#pragma unroll
            for (int dx = 0; dx < ND; ++dx)
#pragma unroll
                for (int j = 0; j < 8; ++j)
                    acc[dx][j] = fmaf(a[j], f[j + dx], acc[dx][j]);
        }

        if (++s_cur >= STAGES) s_cur = 0;
    }

    // ---- direct coalesced stores (mean folded in) ----
    const float scale = 1.0f / 128.0f;
    float* op = out + (((size_t)b * NDD + (size_t)w * ND) * HH + (y0 + tr)) * WW + lb * 8;
#pragma unroll
    for (int dx = 0; dx < ND; ++dx) {
        float4 v0, v1;
        v0.x = acc[dx][0] * scale; v0.y = acc[dx][1] * scale;
        v0.z = acc[dx][2] * scale; v0.w = acc[dx][3] * scale;
        v1.x = acc[dx][4] * scale; v1.y = acc[dx][5] * scale;
        v1.z = acc[dx][6] * scale; v1.w = acc[dx][7] * scale;
        *reinterpret_cast<float4*>(op + (size_t)dx * HH * WW)     = v0;
        *reinterpret_cast<float4*>(op + (size_t)dx * HH * WW + 4) = v1;
    }
}

extern "C" void kernel_launch(void* const* d_in, const int* in_sizes, int n_in,
                              void* d_out, int out_size)
{
    (void)in_sizes; (void)n_in; (void)out_size;
    cudaFuncSetAttribute(corr_kernel,
                         cudaFuncAttributeMaxDynamicSharedMemorySize, SMEM_BYTES);
    const float* in1 = (const float*)d_in[0];
    const float* in2 = (const float*)d_in[1];
    float* out = (float*)d_out;
    corr_kernel<<<dim3(HH / TY, BB), THREADS, SMEM_BYTES>>>(in1, in2, out);
}

// round 6
// speedup vs baseline: 2.4949x; 1.0983x over previous
#include <cuda_runtime.h>
#include <cstdint>

// Correlation cost volume: B=8, C=128, H=W=128, max_disp=4 -> 81 displacements.
// out[b, dy*9+dx, y, x] = (1/C) sum_c in1[b,c,y,x] * in2[b,c,y+dy-4,x+dx-4] (zero pad)
//
// R3: quad-granular (16B) transposed smem -> cp.async.cg 16B loads + LDS.128
//     conflict-free compute loads; packed fma.rn.f32x2 accumulation;
//     CH=8 channels/chunk, 2-stage cp.async pipeline; edge quads pre-zeroed
//     (MD==4 makes boundary quads all-padding).

#define BB 8
#define CC 128
#define HH 128
#define WW 128
#define MD 4
#define ND 9
#define NDD 81
#define TY 2
#define CH 8
#define NCHUNK (CC / CH)        // 16
#define THREADS 288             // 9 warps, warp w = dy
#define S2_RI (TY + 2 * MD)     // 10

#define S1_ROWQ 32              // quads per in1 row (128 floats)
#define S2_ROWQ 34              // quads per in2 row (136 floats incl. pad)
#define S1_Q (CH * TY * S1_ROWQ)        // 512 quads
#define S2_Q (CH * S2_RI * S2_ROWQ)     // 2720 quads
#define STAGE_Q (S1_Q + S2_Q)           // 3232 quads
#define STAGE_BYTES (STAGE_Q * 16)      // 51712
#define SMEM_BYTES (2 * STAGE_BYTES)    // 103424

typedef unsigned long long u64t;

__device__ __forceinline__ void cp16(uint32_t dst, const float* src, int srcsz) {
    asm volatile("cp.async.cg.shared.global [%0], [%1], 16, %2;\n"
                 :: "r"(dst), "l"(src), "r"(srcsz));
}
__device__ __forceinline__ void cp_commit() {
    asm volatile("cp.async.commit_group;\n");
}
#define CP_WAIT(n) asm volatile("cp.async.wait_group %0;\n" :: "n"(n))

__device__ __forceinline__ u64t pk(float lo, float hi) {
    u64t r; asm("mov.b64 %0, {%1,%2};" : "=l"(r) : "f"(lo), "f"(hi)); return r;
}
__device__ __forceinline__ void upk(u64t v, float& lo, float& hi) {
    asm("mov.b64 {%0,%1}, %2;" : "=f"(lo), "=f"(hi) : "l"(v));
}
__device__ __forceinline__ void fma2(u64t& acc, u64t a, u64t b) {
    asm("fma.rn.f32x2 %0, %1, %2, %0;" : "+l"(acc) : "l"(a), "l"(b));
}

// Load channel-chunk cc into stage at shared byte address sbase.
__device__ __forceinline__ void load_chunk(
    int cc, uint32_t sbase,
    const float* __restrict__ in1, const float* __restrict__ in2,
    int b, int y0, int w, int lane)
{
    const size_t cbase = (size_t)(b * CC + cc * CH) * HH * WW;
    const float* g1 = in1 + cbase;
    const float* g2 = in2 + cbase;

    // ---- in1: 16 rows, 32 quads each; lane -> quad=lane ----
    {
        const uint32_t dslot = (uint32_t)((lane & 1) * 16 + (lane >> 1));
#pragma unroll
        for (int r = w; r < CH * TY; r += ND) {
            int c = r >> 1, row = r & 1;
            const float* src = g1 + ((size_t)c * HH + y0 + row) * WW + 4 * lane;
            uint32_t dst = sbase + 16u * ((uint32_t)(c * TY + row) * S1_ROWQ + dslot);
            cp16(dst, src, 16);
        }
    }

    // ---- in2: 80 rows, interior quads q=1..32; lane -> quad=lane+1 ----
    {
        const int q = lane + 1;
        const uint32_t dslot = (uint32_t)((q & 1) * 17 + (q >> 1));
        const uint32_t s2b = sbase + 16u * S1_Q;
        int ri = (w + 2) % ND;      // first in2 row index for this warp
        int c  = 0;
        while (c < CH) {
            int gy = y0 - MD + ri;
            int ok = ((unsigned)gy < HH) ? 16 : 0;
            const float* src = ok ? (g2 + ((size_t)c * HH + gy) * WW + 4 * lane) : g2;
            uint32_t dst = s2b + 16u * ((uint32_t)(c * S2_RI + ri) * S2_ROWQ + dslot);
            cp16(dst, src, ok);
            ri += ND;
            if (ri >= S2_RI) { ri -= S2_RI; ++c; }
        }
    }
}

__global__ __launch_bounds__(THREADS, 2)
void corr_kernel(const float* __restrict__ in1,
                 const float* __restrict__ in2,
                 float* __restrict__ out)
{
    extern __shared__ float sm[];
    const uint32_t smb = (uint32_t)__cvta_generic_to_shared(sm);

    const int y0 = blockIdx.x * TY;
    const int b  = blockIdx.y;

    const int tid  = threadIdx.x;
    const int w    = tid >> 5;          // dy index 0..8
    const int lane = tid & 31;
    const int tr   = lane >> 4;         // output row 0..1
    const int lb   = lane & 15;         // pixels x = 8*lb + j
    const int ri   = tr + w;            // in2 tile row

    // ---- pre-zero the always-padding edge quads (slots 0 and 33) ----
    for (int i = tid; i < 2 * CH * S2_RI * 2; i += THREADS) {   // 320
        int st  = i / (CH * S2_RI * 2);
        int rem = i - st * (CH * S2_RI * 2);
        int row = rem >> 1;
        int slot = (rem & 1) * 33;
        float4* p = reinterpret_cast<float4*>(sm) +
                    (size_t)st * STAGE_Q + S1_Q + row * S2_ROWQ + slot;
        *p = make_float4(0.f, 0.f, 0.f, 0.f);
    }

    u64t acc2[ND][4];
#pragma unroll
    for (int dx = 0; dx < ND; ++dx)
#pragma unroll
        for (int jj = 0; jj < 4; ++jj) acc2[dx][jj] = 0ull;

    load_chunk(0, smb, in1, in2, b, y0, w, lane);
    cp_commit();

    for (int cc = 0; cc < NCHUNK; ++cc) {
        CP_WAIT(0);          // chunk cc resident (this thread's copies)
        __syncthreads();     // all copies visible; prev compute finished (WAR)

        if (cc + 1 < NCHUNK) {
            load_chunk(cc + 1, smb + ((cc + 1) & 1) * STAGE_BYTES,
                       in1, in2, b, y0, w, lane);
        }
        cp_commit();         // commit every iteration (possibly empty)

        // ---- compute chunk cc ----
        const float4* st4 = reinterpret_cast<const float4*>(sm) +
                            (size_t)(cc & 1) * STAGE_Q;
        const float4* s1q = st4 + tr * S1_ROWQ;
        const float4* s2q = st4 + S1_Q + ri * S2_ROWQ;

#pragma unroll
        for (int c = 0; c < CH; ++c) {
            const float4* ar = s1q + c * (TY * S1_ROWQ);
            const float4* fr = s2q + c * (S2_RI * S2_ROWQ);

            float4 A0 = ar[lb];
            float4 A1 = ar[16 + lb];
            float4 F0 = fr[lb];
            float4 F1 = fr[17 + lb];
            float4 F2 = fr[lb + 1];
            float4 F3 = fr[17 + lb + 1];

            float f[16] = { F0.x, F0.y, F0.z, F0.w,  F1.x, F1.y, F1.z, F1.w,
                            F2.x, F2.y, F2.z, F2.w,  F3.x, F3.y, F3.z, F3.w };
            u64t a2[4] = { pk(A0.x, A0.y), pk(A0.z, A0.w),
                           pk(A1.x, A1.y), pk(A1.z, A1.w) };

#pragma unroll
            for (int k = 0; k < 15; ++k) {
                u64t p = pk(f[k], f[k + 1]);
#pragma unroll
                for (int jj = 0; jj < 4; ++jj) {
                    int dx = k - 2 * jj;
                    if (dx >= 0 && dx < ND)
                        fma2(acc2[dx][jj], a2[jj], p);
                }
            }
        }
    }

    // ---- epilogue: scale by 1/C, direct coalesced float4 stores ----
    const float sc = 1.0f / 128.0f;
    float* op = out + (((size_t)b * NDD + (size_t)w * ND) * HH + (y0 + tr)) * WW + lb * 8;
#pragma unroll
    for (int dx = 0; dx < ND; ++dx) {
        float r[8];
#pragma unroll
        for (int jj = 0; jj < 4; ++jj)
            upk(acc2[dx][jj], r[2 * jj], r[2 * jj + 1]);
        float4 v0 = { r[0] * sc, r[1] * sc, r[2] * sc, r[3] * sc };
        float4 v1 = { r[4] * sc, r[5] * sc, r[6] * sc, r[7] * sc };
        *reinterpret_cast<float4*>(op + (size_t)dx * HH * WW)     = v0;
        *reinterpret_cast<float4*>(op + (size_t)dx * HH * WW + 4) = v1;
    }
}

extern "C" void kernel_launch(void* const* d_in, const int* in_sizes, int n_in,
                              void* d_out, int out_size)
{
    (void)in_sizes; (void)n_in; (void)out_size;
    cudaFuncSetAttribute(corr_kernel,
                         cudaFuncAttributeMaxDynamicSharedMemorySize, SMEM_BYTES);
    const float* in1 = (const float*)d_in[0];
    const float* in2 = (const float*)d_in[1];
    float* out = (float*)d_out;
    corr_kernel<<<dim3(HH / TY, BB), THREADS, SMEM_BYTES>>>(in1, in2, out);
}